// round 12
// baseline (speedup 1.0000x reference)
#include <cuda_runtime.h>
#include <cstdint>

#define TT   1000
#define TM1  999
#define BB   64

// ---------------- constants computed by setup kernel ----------------
__device__ float g_tau[256], g_lam[256], g_AtL[256], g_AtLA[256];
__device__ float g_tau_mu[16], g_AtLb[16], g_Lb[16];
__device__ float g_consts[2];          // [0]=trans_const, [1]=init_const
__device__ unsigned g_keys[BB][2];

// ---------------- scratch (device globals; no allocation) ----------------
__device__ float g_scr1[(size_t)BB * TM1 * 256]; // fwd: Pi   -> bwd: K^T
__device__ float g_scr2[(size_t)BB * TM1 * 256]; // fwd: G    -> bwd: Ls
__device__ float g_scr3[(size_t)BB * TT  * 16];  // fwd: Mim  -> bwd: m_t (slot TM1 = m_T)
__device__ float g_eps [(size_t)BB * TT  * 16];  // normal samples

// ---------------- Threefry-2x32 (20 rounds), JAX-compatible ----------------
__device__ __forceinline__ void tf2x32(unsigned k0, unsigned k1,
                                       unsigned x0, unsigned x1,
                                       unsigned &o0, unsigned &o1) {
    unsigned ks2 = k0 ^ k1 ^ 0x1BD11BDAu;
    x0 += k0; x1 += k1;
#define TFR(r) { x0 += x1; x1 = (x1 << (r)) | (x1 >> (32 - (r))); x1 ^= x0; }
    TFR(13) TFR(15) TFR(26) TFR(6)
    x0 += k1;  x1 += ks2 + 1u;
    TFR(17) TFR(29) TFR(16) TFR(24)
    x0 += ks2; x1 += k0 + 2u;
    TFR(13) TFR(15) TFR(26) TFR(6)
    x0 += k0;  x1 += k1 + 3u;
    TFR(17) TFR(29) TFR(16) TFR(24)
    x0 += k1;  x1 += ks2 + 4u;
    TFR(13) TFR(15) TFR(26) TFR(6)
    x0 += ks2; x1 += k0 + 5u;
#undef TFR
    o0 = x0; o1 = x1;
}

// ---- one in-place GJ pivot step on augmented [M(16) | R(16) | m(1)], double-buffered ----
// Left block becomes M^{-1} in place. One barrier per step. Returns the pivot.
__device__ __forceinline__ float gj_step(float (*C)[48], float (*N)[48],
                                         int k, int i, int j) {
    float piv  = C[k][k];
    float pinv = __fdividef(1.f, piv);
    float f    = C[i][k];
    float s0   = C[k][j]      * pinv;
    float s1   = C[k][j + 16] * pinv;
    float sm   = C[k][32]     * pinv;
    float a0   = C[i][j];
    float a1   = C[i][j + 16];
    float am   = C[i][32];
    float r0, r1, rm;
    if (i == k) {
        r0 = (j == k) ? pinv : s0;
        r1 = s1;
        rm = sm;
    } else {
        r0 = (j == k) ? (-f * pinv) : fmaf(-f, s0, a0);
        r1 = fmaf(-f, s1, a1);
        rm = fmaf(-f, sm, am);
    }
    N[i][j]      = r0;
    N[i][j + 16] = r1;
    if (j == 0) N[i][32] = rm;
    __syncthreads();
    return piv;
}

// ---- one Cholesky step (lower), double-buffered, one barrier per step ----
__device__ __forceinline__ void chol_step(float (*C)[48], float (*N)[48],
                                          int k, int i, int j) {
    float dk  = C[k][k];
    float inv = rsqrtf(dk);
    float cik = C[i][k], cjk = C[j][k], cij = C[i][j];
    float r;
    if (j < k)       r = cij;
    else if (j == k) r = (i >= k) ? cik * inv : cij;
    else             r = (i >= j) ? fmaf(-(cik * inv), cjk * inv, cij) : cij;
    N[i][j] = r;
    __syncthreads();
}

// ---------------- setup: shared model constants + batch keys ----------------
__device__ float logdet16_local(const float M[16][17]) {
    float a[16][16];
    for (int r = 0; r < 16; ++r)
        for (int c = 0; c < 16; ++c) a[r][c] = M[r][c];
    float ld = 0.f;
    for (int k = 0; k < 16; ++k) {
        float p = a[k][k];
        ld += logf(p);
        float pi_ = __fdiv_rn(1.f, p);
        for (int r = k + 1; r < 16; ++r) {
            float f = a[r][k] * pi_;
            for (int c = k + 1; c < 16; ++c) a[r][c] = fmaf(-f, a[k][c], a[r][c]);
        }
    }
    return ld;
}

__global__ void __launch_bounds__(256) setup_kernel(const float* __restrict__ loc,
                                                    const float* __restrict__ Tau_p,
                                                    const float* __restrict__ Lam_p,
                                                    const float* __restrict__ X) {
    __shared__ float sTau[16][17], sLamS[16][17], sA[16][17], sAtLs[16][17];
    __shared__ float sbv[16], slocv[16];
    int tid = threadIdx.x, i = tid >> 4, j = tid & 15;

    float t = 0.f, l = 0.f;
#pragma unroll
    for (int k = 0; k < 16; ++k) {
        t = fmaf(Tau_p[i * 16 + k], Tau_p[j * 16 + k], t);
        l = fmaf(Lam_p[i * 16 + k], Lam_p[j * 16 + k], l);
    }
    if (i == j) { t += 1e-8f; l += 1e-8f; }
    sTau[i][j] = t; sLamS[i][j] = l;
    sA[i][j]   = X[i * 17 + j];
    if (tid < 16) { sbv[tid] = X[tid * 17 + 16]; slocv[tid] = loc[tid]; }
    __syncthreads();

    float atl = 0.f;
#pragma unroll
    for (int k = 0; k < 16; ++k) atl = fmaf(sA[k][i], sLamS[k][j], atl);
    sAtLs[i][j] = atl;
    __syncthreads();

    float atla = 0.f;
#pragma unroll
    for (int k = 0; k < 16; ++k) atla = fmaf(sAtLs[i][k], sA[k][j], atla);

    g_tau[tid] = t; g_lam[tid] = l; g_AtL[tid] = atl; g_AtLA[tid] = atla;

    if (tid < 16) {
        float tm = 0.f, alb = 0.f, lb = 0.f;
#pragma unroll
        for (int k = 0; k < 16; ++k) {
            tm  = fmaf(sTau[tid][k],  slocv[k], tm);
            alb = fmaf(sAtLs[tid][k], sbv[k],   alb);
            lb  = fmaf(sLamS[tid][k], sbv[k],   lb);
        }
        g_tau_mu[tid] = tm; g_AtLb[tid] = alb; g_Lb[tid] = lb;
    }
    if (tid < BB) {
        unsigned o0, o1;
        tf2x32(0u, 42u, 0u, (unsigned)tid, o0, o1);
        g_keys[tid][0] = o0; g_keys[tid][1] = o1;
    }
    __syncthreads();
    if (tid == 0) {
        float ldl = logdet16_local(sLamS);
        float ldt = logdet16_local(sTau);
        float bLb = 0.f, ltm = 0.f;
        for (int k = 0; k < 16; ++k) {
            bLb = fmaf(sbv[k],   g_Lb[k],     bLb);
            ltm = fmaf(slocv[k], g_tau_mu[k], ltm);
        }
        g_consts[0] = -0.5f * bLb + 0.5f * ldl;  // trans_const
        g_consts[1] = -0.5f * ltm + 0.5f * ldt;  // init_const
    }
}

// ---------------- main: per-batch forward / backward / sample ----------------
__global__ void __launch_bounds__(256, 1) lds_main(const float* __restrict__ Jr,
                                                   const float* __restrict__ hr,
                                                   float* __restrict__ out) {
    const int b   = blockIdx.x;
    const int tid = threadIdx.x;
    const int i   = tid >> 4, j = tid & 15;

    const float trans_const = g_consts[0];
    const float init_const  = g_consts[1];

    const float* Jb = Jr + (size_t)b * TT * 16;
    const float* Hb = hr + (size_t)b * TT * 16;
    float* scr1 = g_scr1 + (size_t)b * TM1 * 256;
    float* scr2 = g_scr2 + (size_t)b * TM1 * 256;
    float* scr3 = g_scr3 + (size_t)b * TT * 16;
    float* epsb = g_eps  + (size_t)b * TT * 16;

    const size_t KL_OFF    = (size_t)BB * TT * 16;
    const size_t EXXT_OFF  = KL_OFF + BB;
    const size_t EX_OFF    = EXXT_OFF + (size_t)BB * TT * 256;
    const size_t EXXNT_OFF = EX_OFF + (size_t)BB * TT * 16;
    float* zO     = out + (size_t)b * TT * 16;
    float* exxtO  = out + EXXT_OFF + (size_t)b * TT * 256;
    float* exO    = out + EX_OFF + (size_t)b * TT * 16;
    float* exxntO = out + EXXNT_OFF + (size_t)b * TM1 * 256;

    __shared__ float B[2][16][48];               // GJ / chol ping-pong
    __shared__ float sAtL[16][17];
    __shared__ float Gm[16][17], Wb[16][17], Vn[16][17];
    __shared__ float fh[16], mv[16], nJ[16], nH[16];
    __shared__ float mt_s[16], mn[16], vtd[16], sAtLb[16];
    __shared__ float nJb[16], nHb[16];
    __shared__ float xs[2][16];

    // ---- epsilon generation (partitionable random_bits: lane0 ^ lane1) ----
    {
        unsigned k0 = g_keys[b][0], k1 = g_keys[b][1];
        for (int idx = tid; idx < TT * 16; idx += 256) {
            unsigned o0, o1;
            tf2x32(k0, k1, 0u, (unsigned)idx, o0, o1);
            unsigned bits = o0 ^ o1;
            float f = __uint_as_float((bits >> 9) | 0x3f800000u) - 1.0f;
            const float lo = -0.99999994f;
            float v = fmaxf(lo, f * 2.0f + lo);
            epsb[idx] = 1.4142135623730951f * erfinvf(v);
        }
    }

    // ---- constants + initial carry ----
    const float lam_r  = g_lam[tid];
    const float atla_r = g_AtLA[tid];
    sAtL[i][j] = g_AtL[tid];
    float fJ_r = g_tau[tid] + ((i == j) ? (Jb[i] + 0.5f) : 0.f);
    float lb_r = 0.f, jn_r = 0.f, hn_r = 0.f;
    if (tid < 16) {
        sAtLb[tid] = g_AtLb[tid];
        fh[tid]    = g_tau_mu[tid] + Hb[tid];
        lb_r = g_Lb[tid];
        jn_r = Jb[16 + tid];   // J/H at t=1, prefetched
        hn_r = Hb[16 + tid];
    }
    __syncthreads();

    float lz = 0.f, klacc = 0.f;

    // ======================= FORWARD FILTER (18 barriers/step) =======================
    for (int t = 0; t < TM1; ++t) {
        B[0][i][j]      = fJ_r + atla_r;         // M
        B[0][i][j + 16] = sAtL[i][j];            // -> G
        if (j == 0) B[0][i][32] = fh[i] - sAtLb[i];  // m -> Mim
        if (tid < 16) {
            mv[tid] = fh[tid] - sAtLb[tid];
            nJ[tid] = jn_r + 0.5f; nH[tid] = hn_r;
            int tn = t + 2;
            if (tn < TT) { jn_r = Jb[tn * 16 + tid]; hn_r = Hb[tn * 16 + tid]; }
        }
        __syncthreads();

        float pp1 = 1.f, pp2 = 1.f;
#pragma unroll
        for (int k = 0; k < 16; k += 2) {
            float pa = gj_step(B[0], B[1], k,     i, j);
            float pb = gj_step(B[1], B[0], k + 1, i, j);
            if (k < 8) { pp1 *= pa; pp1 *= pb; } else { pp2 *= pa; pp2 *= pb; }
        }
        // B[0] = [Pi | G | Mim]
        scr1[(size_t)t * 256 + tid] = B[0][i][j];
        scr2[(size_t)t * 256 + tid] = B[0][i][j + 16];
        if (tid < 16) scr3[(size_t)t * 16 + tid] = B[0][tid][32];

        float dot = 0.f;
#pragma unroll
        for (int k = 0; k < 16; ++k) dot = fmaf(mv[k], B[0][k][32], dot);
        lz += 0.5f * dot - 0.5f * (__logf(pp1) + __logf(pp2)) + trans_const;

        float nfJ = lam_r;
#pragma unroll
        for (int k = 0; k < 16; ++k) nfJ = fmaf(-sAtL[k][i], B[0][k][16 + j], nfJ);
        if (i == j) nfJ += nJ[i];
        if (tid < 16) {
            float s = lb_r;
#pragma unroll
            for (int k = 0; k < 16; ++k) s = fmaf(sAtL[k][tid], B[0][k][32], s);
            fh[tid] = s + nH[tid];               // old fh last read before GJ; safe
        }
        __syncthreads();
        fJ_r = nfJ;
    }

    // ---- terminal: invert fJ_T with fh as RHS ----
    B[0][i][j] = fJ_r;
    if (j == 0) B[0][i][32] = fh[i];
    __syncthreads();
    {
        float pp1 = 1.f, pp2 = 1.f;
#pragma unroll
        for (int k = 0; k < 16; k += 2) {
            float pa = gj_step(B[0], B[1], k,     i, j);
            float pb = gj_step(B[1], B[0], k + 1, i, j);
            if (k < 8) { pp1 *= pa; pp1 *= pb; } else { pp2 *= pa; pp2 *= pb; }
        }
        float dotT = 0.f;
#pragma unroll
        for (int k = 0; k < 16; ++k) dotT = fmaf(fh[k], B[0][k][32], dotT);
        lz += init_const + 0.5f * dotT - 0.5f * (__logf(pp1) + __logf(pp2));
    }
    float logZ = lz;
    if (tid < 16) mt_s[tid] = B[0][tid][32];     // m_T
    __syncthreads();
    exxtO[(size_t)(TT - 1) * 256 + tid] = B[0][i][j] + mt_s[i] * mt_s[j];
    if (tid < 16) {
        exO[(size_t)(TT - 1) * 16 + tid] = mt_s[tid];
        scr3[(size_t)TM1 * 16 + tid]     = mt_s[tid];
    }
    {
        float s = 0.f;
#pragma unroll
        for (int k = 0; k < 16; ++k)
            s += -0.5f * nJ[k] * (B[0][k][k] + mt_s[k] * mt_s[k]) + nH[k] * mt_s[k];
        klacc += s;
    }
    Vn[i][j] = B[0][i][j];
    if (tid < 16) mn[tid] = mt_s[tid];
    __syncthreads();

    // ======================= BACKWARD SMOOTHER (37 barriers/step) =======================
    float g_r  = scr2[(size_t)(TM1 - 1) * 256 + tid];
    float pi_r = scr1[(size_t)(TM1 - 1) * 256 + tid];
    float mim_r = 0.f, jb_r = 0.f, hb_r = 0.f;
    if (tid < 16) {
        mim_r = scr3[(size_t)(TM1 - 1) * 16 + tid];
        jb_r  = Jb[(TM1 - 1) * 16 + tid];
        hb_r  = Hb[(TM1 - 1) * 16 + tid];
    }
    for (int t = TM1 - 1; t >= 0; --t) {
        Gm[i][j] = g_r;
        float pi_c  = pi_r;
        float mim_c = mim_r;
        if (tid < 16) { nJb[tid] = jb_r + 0.5f; nHb[tid] = hb_r; }
        if (t > 0) {                              // prefetch t-1
            g_r  = scr2[(size_t)(t - 1) * 256 + tid];
            pi_r = scr1[(size_t)(t - 1) * 256 + tid];
            if (tid < 16) {
                mim_r = scr3[(size_t)(t - 1) * 16 + tid];
                jb_r  = Jb[(t - 1) * 16 + tid];
                hb_r  = Hb[(t - 1) * 16 + tid];
            }
        }
        __syncthreads();                          // b1

        float w = 0.f;
#pragma unroll
        for (int k = 0; k < 16; ++k) w = fmaf(Gm[i][k], Vn[k][j], w);
        Wb[i][j] = w;
        if (tid < 16) {
            float s = mim_c;
#pragma unroll
            for (int k = 0; k < 16; ++k) s = fmaf(Gm[tid][k], mn[k], s);
            mt_s[tid] = s;
        }
        __syncthreads();                          // b2

        float v = pi_c;
#pragma unroll
        for (int k = 0; k < 16; ++k) v = fmaf(Wb[i][k], Gm[j][k], v);
        exxtO [(size_t)t * 256 + tid] = v + mt_s[i] * mt_s[j];
        exxntO[(size_t)t * 256 + tid] = w + mt_s[i] * mn[j];
        if (tid < 16) {
            exO[(size_t)t * 16 + tid]  = mt_s[tid];
            scr3[(size_t)t * 16 + tid] = mt_s[tid];
        }
        B[0][i][j]      = v;                      // Vt
        B[0][i][j + 16] = w;                      // C
        if (j == 0) B[0][i][32] = 0.f;
        if (i == j) vtd[i] = v;
        __syncthreads();                          // b3

        {
            float s = 0.f;
#pragma unroll
            for (int k = 0; k < 16; ++k)
                s += -0.5f * nJb[k] * (vtd[k] + mt_s[k] * mt_s[k]) + nHb[k] * mt_s[k];
            klacc += s;
        }
#pragma unroll
        for (int k = 0; k < 16; k += 2) {         // K = Vt^{-1} C
            gj_step(B[0], B[1], k,     i, j);
            gj_step(B[1], B[0], k + 1, i, j);
        }
        float cv = Vn[i][j];
#pragma unroll
        for (int k = 0; k < 16; ++k) cv = fmaf(-Wb[k][i], B[0][k][16 + j], cv);
        if (i == j) cv += 1e-6f;                  // JITTER
        scr1[(size_t)t * 256 + tid] = B[0][j][16 + i];   // K^T
        B[0][i][j] = cv;                          // disjoint from cols 16..31 reads
        __syncthreads();                          // b4
#pragma unroll
        for (int k = 0; k < 16; k += 2) {         // Ls = chol(condV)
            chol_step(B[0], B[1], k,     i, j);
            chol_step(B[1], B[0], k + 1, i, j);
        }
        scr2[(size_t)t * 256 + tid] = (j <= i) ? B[0][i][j] : 0.f;
        Vn[i][j] = v;                             // next step reads after its b1
        if (tid < 16) mn[tid] = mt_s[tid];
    }
    __syncthreads();

    // ======================= SAMPLING (1 barrier/step) =======================
    B[0][i][j] = Vn[i][j] + ((i == j) ? 1e-6f : 0.f);
    __syncthreads();
#pragma unroll
    for (int k = 0; k < 16; k += 2) {
        chol_step(B[0], B[1], k,     i, j);
        chol_step(B[1], B[0], k + 1, i, j);
    }
    {
        float e0 = epsb[j];
        float v  = ((j <= i) ? B[0][i][j] : 0.f) * e0;
        v += __shfl_xor_sync(0xffffffffu, v, 1);
        v += __shfl_xor_sync(0xffffffffu, v, 2);
        v += __shfl_xor_sync(0xffffffffu, v, 4);
        v += __shfl_xor_sync(0xffffffffu, v, 8);
        if (j == 0) { float x = mn[i] + v; xs[0][i] = x; zO[i] = x; }
    }
    __syncthreads();

    float kt_r  = scr1[tid];
    float ls_r  = scr2[tid];
    float mtj_r = scr3[j];
    float mni_r = scr3[16 + i];
    float ej_r  = epsb[16 + j];
    for (int t = 0; t < TM1; ++t) {
        float kt = kt_r, ls = ls_r, mtj = mtj_r, mni = mni_r, ej = ej_r;
        if (t + 1 < TM1) {                        // prefetch t+1
            kt_r  = scr1[(size_t)(t + 1) * 256 + tid];
            ls_r  = scr2[(size_t)(t + 1) * 256 + tid];
            mtj_r = scr3[(size_t)(t + 1) * 16 + j];
            mni_r = scr3[(size_t)(t + 2) * 16 + i];
            ej_r  = epsb[(size_t)(t + 2) * 16 + j];
        }
        float v = kt * (xs[t & 1][j] - mtj) + ls * ej;
        v += __shfl_xor_sync(0xffffffffu, v, 1);
        v += __shfl_xor_sync(0xffffffffu, v, 2);
        v += __shfl_xor_sync(0xffffffffu, v, 4);
        v += __shfl_xor_sync(0xffffffffu, v, 8);
        if (j == 0) {
            float x = mni + v;
            xs[(t & 1) ^ 1][i] = x;
            zO[(size_t)(t + 1) * 16 + i] = x;
        }
        __syncthreads();
    }

    if (tid == 0) out[KL_OFF + b] = klacc - logZ;
}

// ---------------- launch ----------------
extern "C" void kernel_launch(void* const* d_in, const int* in_sizes, int n_in,
                              void* d_out, int out_size) {
    const float* Jr    = (const float*)d_in[0];
    const float* hr    = (const float*)d_in[1];
    const float* loc   = (const float*)d_in[2];
    const float* Tau_p = (const float*)d_in[3];
    const float* Lam_p = (const float*)d_in[4];
    const float* X     = (const float*)d_in[5];
    float* out = (float*)d_out;

    setup_kernel<<<1, 256>>>(loc, Tau_p, Lam_p, X);
    lds_main<<<BB, 256>>>(Jr, hr, out);
}

// round 13
// speedup vs baseline: 1.2298x; 1.2298x over previous
#include <cuda_runtime.h>
#include <cstdint>

#define TT   1000
#define TM1  999
#define BB   64

__device__ float g_tau[256], g_lam[256], g_AtL[256], g_AtLA[256];
__device__ float g_tau_mu[16], g_AtLb[16], g_Lb[16];
__device__ float g_consts[2];
__device__ unsigned g_keys[BB][2];

__device__ float g_scr1[(size_t)BB * TM1 * 256]; // fwd: Pi   -> bwd: K^T
__device__ float g_scr2[(size_t)BB * TM1 * 256]; // fwd: G    -> bwd: Ls
__device__ float g_scr3[(size_t)BB * TT  * 16];  // fwd: Mim  -> bwd: m_t (slot TM1=m_T)
__device__ float g_eps [(size_t)BB * TT  * 16];

__device__ __forceinline__ void tf2x32(unsigned k0, unsigned k1,
                                       unsigned x0, unsigned x1,
                                       unsigned &o0, unsigned &o1) {
    unsigned ks2 = k0 ^ k1 ^ 0x1BD11BDAu;
    x0 += k0; x1 += k1;
#define TFR(r) { x0 += x1; x1 = (x1 << (r)) | (x1 >> (32 - (r))); x1 ^= x0; }
    TFR(13) TFR(15) TFR(26) TFR(6)
    x0 += k1;  x1 += ks2 + 1u;
    TFR(17) TFR(29) TFR(16) TFR(24)
    x0 += ks2; x1 += k0 + 2u;
    TFR(13) TFR(15) TFR(26) TFR(6)
    x0 += k0;  x1 += k1 + 3u;
    TFR(17) TFR(29) TFR(16) TFR(24)
    x0 += k1;  x1 += ks2 + 4u;
    TFR(13) TFR(15) TFR(26) TFR(6)
    x0 += ks2; x1 += k0 + 5u;
#undef TFR
    o0 = x0; o1 = x1;
}

// 4x4 inverse via adjugate; returns det
__device__ __forceinline__ float inv4x4(const float m[16], float inv[16]) {
    float s0 = m[0]*m[5] - m[4]*m[1];
    float s1 = m[0]*m[6] - m[4]*m[2];
    float s2 = m[0]*m[7] - m[4]*m[3];
    float s3 = m[1]*m[6] - m[5]*m[2];
    float s4 = m[1]*m[7] - m[5]*m[3];
    float s5 = m[2]*m[7] - m[6]*m[3];
    float c5 = m[10]*m[15] - m[14]*m[11];
    float c4 = m[9]*m[15]  - m[13]*m[11];
    float c3 = m[9]*m[14]  - m[13]*m[10];
    float c2 = m[8]*m[15]  - m[12]*m[11];
    float c1 = m[8]*m[14]  - m[12]*m[10];
    float c0 = m[8]*m[13]  - m[12]*m[9];
    float det = s0*c5 - s1*c4 + s2*c3 + s3*c2 - s4*c1 + s5*c0;
    float id = __fdividef(1.f, det);
    inv[0]  = ( m[5]*c5 - m[6]*c4 + m[7]*c3) * id;
    inv[1]  = (-m[1]*c5 + m[2]*c4 - m[3]*c3) * id;
    inv[2]  = ( m[13]*s5 - m[14]*s4 + m[15]*s3) * id;
    inv[3]  = (-m[9]*s5 + m[10]*s4 - m[11]*s3) * id;
    inv[4]  = (-m[4]*c5 + m[6]*c2 - m[7]*c1) * id;
    inv[5]  = ( m[0]*c5 - m[2]*c2 + m[3]*c1) * id;
    inv[6]  = (-m[12]*s5 + m[14]*s2 - m[15]*s1) * id;
    inv[7]  = ( m[8]*s5 - m[10]*s2 + m[11]*s1) * id;
    inv[8]  = ( m[4]*c4 - m[5]*c2 + m[7]*c0) * id;
    inv[9]  = (-m[0]*c4 + m[1]*c2 - m[3]*c0) * id;
    inv[10] = ( m[12]*s4 - m[13]*s2 + m[15]*s0) * id;
    inv[11] = (-m[8]*s4 + m[9]*s2 - m[11]*s0) * id;
    inv[12] = (-m[4]*c3 + m[5]*c1 - m[6]*c0) * id;
    inv[13] = ( m[0]*c3 - m[1]*c1 + m[2]*c0) * id;
    inv[14] = (-m[12]*s3 + m[13]*s1 - m[14]*s0) * id;
    inv[15] = ( m[8]*s3 - m[9]*s1 + m[10]*s0) * id;
    return det;
}

// blocked GJ step: pivots [k0,k0+4) on augmented [M(16)|R(16)|m]; C->N; sync at end.
template <bool WITH_M>
__device__ __forceinline__ float gj_block(const float (*C)[48], float (*N)[48],
                                          int k0, int i, int j) {
    float D[16], Di[16];
#pragma unroll
    for (int r = 0; r < 4; ++r)
#pragma unroll
        for (int c = 0; c < 4; ++c) D[r*4+c] = C[k0+r][k0+c];
    float det = inv4x4(D, Di);

    float u0 = C[i][k0+0], u1 = C[i][k0+1], u2 = C[i][k0+2], u3 = C[i][k0+3];
    bool iin = ((unsigned)(i - k0)) < 4u;
    int  il  = i - k0;

    { // left column j
        float res;
        if (((unsigned)(j - k0)) < 4u) {
            int jl = j - k0;
            if (iin) res = Di[il*4 + jl];
            else     res = -(u0*Di[jl] + u1*Di[4+jl] + u2*Di[8+jl] + u3*Di[12+jl]);
        } else {
            float b0=C[k0+0][j], b1=C[k0+1][j], b2=C[k0+2][j], b3=C[k0+3][j];
            float w0 = Di[0]*b0  + Di[1]*b1  + Di[2]*b2  + Di[3]*b3;
            float w1 = Di[4]*b0  + Di[5]*b1  + Di[6]*b2  + Di[7]*b3;
            float w2 = Di[8]*b0  + Di[9]*b1  + Di[10]*b2 + Di[11]*b3;
            float w3 = Di[12]*b0 + Di[13]*b1 + Di[14]*b2 + Di[15]*b3;
            if (iin) res = (il==0) ? w0 : (il==1) ? w1 : (il==2) ? w2 : w3;
            else     res = C[i][j] - (u0*w0 + u1*w1 + u2*w2 + u3*w3);
        }
        N[i][j] = res;
    }
    { // right column j+16
        float b0=C[k0+0][j+16], b1=C[k0+1][j+16], b2=C[k0+2][j+16], b3=C[k0+3][j+16];
        float w0 = Di[0]*b0  + Di[1]*b1  + Di[2]*b2  + Di[3]*b3;
        float w1 = Di[4]*b0  + Di[5]*b1  + Di[6]*b2  + Di[7]*b3;
        float w2 = Di[8]*b0  + Di[9]*b1  + Di[10]*b2 + Di[11]*b3;
        float w3 = Di[12]*b0 + Di[13]*b1 + Di[14]*b2 + Di[15]*b3;
        float res;
        if (iin) res = (il==0) ? w0 : (il==1) ? w1 : (il==2) ? w2 : w3;
        else     res = C[i][j+16] - (u0*w0 + u1*w1 + u2*w2 + u3*w3);
        N[i][j+16] = res;
    }
    if (WITH_M && j == 0) {
        float b0=C[k0+0][32], b1=C[k0+1][32], b2=C[k0+2][32], b3=C[k0+3][32];
        float w0 = Di[0]*b0  + Di[1]*b1  + Di[2]*b2  + Di[3]*b3;
        float w1 = Di[4]*b0  + Di[5]*b1  + Di[6]*b2  + Di[7]*b3;
        float w2 = Di[8]*b0  + Di[9]*b1  + Di[10]*b2 + Di[11]*b3;
        float w3 = Di[12]*b0 + Di[13]*b1 + Di[14]*b2 + Di[15]*b3;
        float res;
        if (iin) res = (il==0) ? w0 : (il==1) ? w1 : (il==2) ? w2 : w3;
        else     res = C[i][32] - (u0*w0 + u1*w1 + u2*w2 + u3*w3);
        N[i][32] = res;
    }
    __syncthreads();
    return det;
}

// blocked Cholesky (lower): cols [k0,k0+4); C->N (left 16 cols); sync at end.
__device__ __forceinline__ void chol_block(const float (*C)[48], float (*N)[48],
                                           int k0, int i, int j) {
    float d00=C[k0+0][k0+0];
    float d10=C[k0+1][k0+0], d11=C[k0+1][k0+1];
    float d20=C[k0+2][k0+0], d21=C[k0+2][k0+1], d22=C[k0+2][k0+2];
    float d30=C[k0+3][k0+0], d31=C[k0+3][k0+1], d32=C[k0+3][k0+2], d33=C[k0+3][k0+3];
    float r0 = rsqrtf(d00);
    float l00 = d00*r0, l10 = d10*r0, l20 = d20*r0, l30 = d30*r0;
    float t11 = d11 - l10*l10;            float r1 = rsqrtf(t11);
    float l11 = t11*r1;
    float l21 = (d21 - l20*l10)*r1, l31 = (d31 - l30*l10)*r1;
    float t22 = d22 - l20*l20 - l21*l21;  float r2 = rsqrtf(t22);
    float l22 = t22*r2;
    float l32 = (d32 - l30*l20 - l31*l21)*r2;
    float t33 = d33 - l30*l30 - l31*l31 - l32*l32; float r3 = rsqrtf(t33);
    float l33 = t33*r3;

    float res = C[i][j];
    if (j >= k0) {
        float ui0=C[i][k0+0], ui1=C[i][k0+1], ui2=C[i][k0+2], ui3=C[i][k0+3];
        float p0 = ui0*r0;
        float p1 = (ui1 - p0*l10)*r1;
        float p2 = (ui2 - p0*l20 - p1*l21)*r2;
        float p3 = (ui3 - p0*l30 - p1*l31 - p2*l32)*r3;
        if (j < k0 + 4) {
            int jl = j - k0;
            if (((unsigned)(i - k0)) < 4u) {
                int il = i - k0;
                float v = 0.f;
                if (jl == 0)      v = (il==0)?l00:(il==1)?l10:(il==2)?l20:l30;
                else if (jl == 1) v = (il==1)?l11:(il==2)?l21:(il==3)?l31:0.f;
                else if (jl == 2) v = (il==2)?l22:(il==3)?l32:0.f;
                else              v = (il==3)?l33:0.f;
                res = v;
            } else if (i >= k0 + 4) {
                res = (jl==0)?p0:(jl==1)?p1:(jl==2)?p2:p3;
            }
        } else {
            float uj0=C[j][k0+0], uj1=C[j][k0+1], uj2=C[j][k0+2], uj3=C[j][k0+3];
            float q0 = uj0*r0;
            float q1 = (uj1 - q0*l10)*r1;
            float q2 = (uj2 - q0*l20 - q1*l21)*r2;
            float q3 = (uj3 - q0*l30 - q1*l31 - q2*l32)*r3;
            res = res - (p0*q0 + p1*q1 + p2*q2 + p3*q3);
        }
    }
    N[i][j] = res;
    __syncthreads();
}

__device__ float logdet16_local(const float M[16][17]) {
    float a[16][16];
    for (int r = 0; r < 16; ++r)
        for (int c = 0; c < 16; ++c) a[r][c] = M[r][c];
    float ld = 0.f;
    for (int k = 0; k < 16; ++k) {
        float p = a[k][k];
        ld += logf(p);
        float pi_ = __fdiv_rn(1.f, p);
        for (int r = k + 1; r < 16; ++r) {
            float f = a[r][k] * pi_;
            for (int c = k + 1; c < 16; ++c) a[r][c] = fmaf(-f, a[k][c], a[r][c]);
        }
    }
    return ld;
}

__global__ void __launch_bounds__(256) setup_kernel(const float* __restrict__ loc,
                                                    const float* __restrict__ Tau_p,
                                                    const float* __restrict__ Lam_p,
                                                    const float* __restrict__ X) {
    __shared__ float sTau[16][17], sLamS[16][17], sA[16][17], sAtLs[16][17];
    __shared__ float sbv[16], slocv[16];
    int tid = threadIdx.x, i = tid >> 4, j = tid & 15;

    float t = 0.f, l = 0.f;
#pragma unroll
    for (int k = 0; k < 16; ++k) {
        t = fmaf(Tau_p[i * 16 + k], Tau_p[j * 16 + k], t);
        l = fmaf(Lam_p[i * 16 + k], Lam_p[j * 16 + k], l);
    }
    if (i == j) { t += 1e-8f; l += 1e-8f; }
    sTau[i][j] = t; sLamS[i][j] = l;
    sA[i][j]   = X[i * 17 + j];
    if (tid < 16) { sbv[tid] = X[tid * 17 + 16]; slocv[tid] = loc[tid]; }
    __syncthreads();

    float atl = 0.f;
#pragma unroll
    for (int k = 0; k < 16; ++k) atl = fmaf(sA[k][i], sLamS[k][j], atl);
    sAtLs[i][j] = atl;
    __syncthreads();

    float atla = 0.f;
#pragma unroll
    for (int k = 0; k < 16; ++k) atla = fmaf(sAtLs[i][k], sA[k][j], atla);

    g_tau[tid] = t; g_lam[tid] = l; g_AtL[tid] = atl; g_AtLA[tid] = atla;

    if (tid < 16) {
        float tm = 0.f, alb = 0.f, lb = 0.f;
#pragma unroll
        for (int k = 0; k < 16; ++k) {
            tm  = fmaf(sTau[tid][k],  slocv[k], tm);
            alb = fmaf(sAtLs[tid][k], sbv[k],   alb);
            lb  = fmaf(sLamS[tid][k], sbv[k],   lb);
        }
        g_tau_mu[tid] = tm; g_AtLb[tid] = alb; g_Lb[tid] = lb;
    }
    if (tid < BB) {
        unsigned o0, o1;
        tf2x32(0u, 42u, 0u, (unsigned)tid, o0, o1);
        g_keys[tid][0] = o0; g_keys[tid][1] = o1;
    }
    __syncthreads();
    if (tid == 0) {
        float ldl = logdet16_local(sLamS);
        float ldt = logdet16_local(sTau);
        float bLb = 0.f, ltm = 0.f;
        for (int k = 0; k < 16; ++k) {
            bLb = fmaf(sbv[k],   g_Lb[k],     bLb);
            ltm = fmaf(slocv[k], g_tau_mu[k], ltm);
        }
        g_consts[0] = -0.5f * bLb + 0.5f * ldl;
        g_consts[1] = -0.5f * ltm + 0.5f * ldt;
    }
}

__global__ void __launch_bounds__(256, 1) lds_main(const float* __restrict__ Jr,
                                                   const float* __restrict__ hr,
                                                   float* __restrict__ out) {
    const int b   = blockIdx.x;
    const int tid = threadIdx.x;
    const int i   = tid >> 4, j = tid & 15;
    const bool isdiag = (i == j);
    const bool isv    = (j == 0);

    const float trans_const = g_consts[0];
    const float init_const  = g_consts[1];

    const float* Jb = Jr + (size_t)b * TT * 16;
    const float* Hb = hr + (size_t)b * TT * 16;
    float* scr1 = g_scr1 + (size_t)b * TM1 * 256;
    float* scr2 = g_scr2 + (size_t)b * TM1 * 256;
    float* scr3 = g_scr3 + (size_t)b * TT * 16;
    float* epsb = g_eps  + (size_t)b * TT * 16;

    const size_t KL_OFF    = (size_t)BB * TT * 16;
    const size_t EXXT_OFF  = KL_OFF + BB;
    const size_t EX_OFF    = EXXT_OFF + (size_t)BB * TT * 256;
    const size_t EXXNT_OFF = EX_OFF + (size_t)BB * TT * 16;
    float* zO     = out + (size_t)b * TT * 16;
    float* exxtO  = out + EXXT_OFF + (size_t)b * TT * 256;
    float* exO    = out + EX_OFF + (size_t)b * TT * 16;
    float* exxntO = out + EXXNT_OFF + (size_t)b * TM1 * 256;

    __shared__ float Buf0[16][48], Buf1[16][48];
    __shared__ float sAtL[16][17];
    __shared__ float Gm[16][17], Wb[16][17], Vn[16][17];
    __shared__ float mt_s[16], mn[16], mT_s[16];
    __shared__ float xs[2][16];
    __shared__ float red[32];

    // ---- epsilon generation ----
    {
        unsigned k0 = g_keys[b][0], k1 = g_keys[b][1];
        for (int idx = tid; idx < TT * 16; idx += 256) {
            unsigned o0, o1;
            tf2x32(k0, k1, 0u, (unsigned)idx, o0, o1);
            unsigned bits = o0 ^ o1;
            float f = __uint_as_float((bits >> 9) | 0x3f800000u) - 1.0f;
            const float lo = -0.99999994f;
            float v = fmaxf(lo, f * 2.0f + lo);
            epsb[idx] = 1.4142135623730951f * erfinvf(v);
        }
    }

    const float lam_r  = g_lam[tid];
    const float atla_r = g_AtLA[tid];
    const float atl_r  = g_AtL[tid];
    sAtL[i][j] = atl_r;
    const float lb_r   = g_Lb[i];     // row constant (used by j==0)
    const float atlb_r = g_AtLb[i];

    // per-role accumulators
    float lzall = 0.f;       // all threads (identical)
    float lzp   = 0.f;       // j==0 threads
    float klacc = 0.f;       // diag threads
    float jn_r = 0.f, hn_r = 0.f;   // diag & j==0 prefetch streams (J/H at t+1)
    float mv_r = 0.f;               // j==0: staged m value

    // ---- pre-stage step 0 ----
    {
        float fJ0 = g_tau[tid] + (isdiag ? (Jb[i] + 0.5f) : 0.f);
        Buf0[i][j]      = fJ0 + atla_r;
        Buf0[i][j + 16] = atl_r;
        if (isv) {
            float fh0 = g_tau_mu[i] + Hb[i];
            mv_r = fh0 - atlb_r;
            Buf0[i][32] = mv_r;
        }
        if (isdiag || isv) { jn_r = Jb[16 + i]; hn_r = Hb[16 + i]; }
    }
    __syncthreads();

    float (*S)[48] = Buf0;
    float (*R)[48] = Buf1;

    // ======================= FORWARD (5 regions/step) =======================
    for (int t = 0; t < TM1; ++t) {
        float d0 = gj_block<true>(S, R, 0,  i, j);
        float d1 = gj_block<true>(R, S, 4,  i, j);
        float d2 = gj_block<true>(S, R, 8,  i, j);
        float d3 = gj_block<true>(R, S, 12, i, j);
        // S = [Pi | G | Mim]
        lzall += trans_const - 0.5f * (__logf(d0 * d1) + __logf(d2 * d3));

        const bool term = (t == TM1 - 1);
        scr1[(size_t)t * 256 + tid] = S[i][j];
        scr2[(size_t)t * 256 + tid] = S[i][16 + j];

        float nfJ = lam_r;
#pragma unroll
        for (int k = 0; k < 16; ++k) nfJ = fmaf(-sAtL[k][i], S[k][16 + j], nfJ);
        R[i][j]      = nfJ + (isdiag ? (jn_r + 0.5f) : 0.f) + (term ? 0.f : atla_r);
        R[i][j + 16] = atl_r;

        if (isv) {
            float mim_i = S[i][32];
            scr3[(size_t)t * 16 + i] = mim_i;
            lzp += 0.5f * mv_r * mim_i;
            float fh_new = lb_r + hn_r;
#pragma unroll
            for (int k = 0; k < 16; ++k) fh_new = fmaf(sAtL[k][i], S[k][32], fh_new);
            mv_r = term ? fh_new : (fh_new - atlb_r);
            R[i][32] = mv_r;
        }
        if ((isdiag || isv) && (t + 2 < TT)) {
            jn_r = Jb[(t + 2) * 16 + i];
            hn_r = Hb[(t + 2) * 16 + i];
        }
        __syncthreads();
        float (*tmp)[48] = S; S = R; R = tmp;
    }

    // ---- terminal inversion: S holds [fJ_T | AtL | fh_T] ----
    {
        float d0 = gj_block<true>(S, R, 0,  i, j);
        float d1 = gj_block<true>(R, S, 4,  i, j);
        float d2 = gj_block<true>(S, R, 8,  i, j);
        float d3 = gj_block<true>(R, S, 12, i, j);
        lzall += init_const - 0.5f * (__logf(d0 * d1) + __logf(d2 * d3));
    }
    // region A: mT out + lzp terminal
    if (isv) {
        float mT = S[i][32];
        mT_s[i] = mT;
        lzp += 0.5f * mv_r * mT;
        exO[(size_t)(TT - 1) * 16 + i] = mT;
        scr3[(size_t)TM1 * 16 + i]     = mT;
    }
    __syncthreads();
    // region B: V_T outputs, klacc terminal, backward init
    {
        float vT = S[i][j];
        float mTi = mT_s[i], mTj = mT_s[j];
        exxtO[(size_t)(TT - 1) * 256 + tid] = vT + mTi * mTj;
        Vn[i][j] = vT;
        if (isdiag) {
            // jn_r/hn_r hold J/H[TT-1]
            klacc += -0.5f * (jn_r + 0.5f) * (vT + mTi * mTi) + hn_r * mTi;
        }
        if (isv) mn[i] = mT_s[i];
    }
    // backward prefetch (t = TM1-1)
    float g_r  = scr2[(size_t)(TM1 - 1) * 256 + tid];
    float pi_r = scr1[(size_t)(TM1 - 1) * 256 + tid];
    float mim_r = 0.f;
    if (isv)    mim_r = scr3[(size_t)(TM1 - 1) * 16 + i];
    if (isdiag) { jn_r = Jb[(TM1 - 1) * 16 + i]; hn_r = Hb[(TM1 - 1) * 16 + i]; }
    Gm[i][j] = g_r;
    __syncthreads();

    float v_reg = 0.f;
    // ======================= BACKWARD (12 regions/step) =======================
    for (int t = TM1 - 1; t >= 0; --t) {
        // R2: Wb = G Vn ; mt
        float w = 0.f;
#pragma unroll
        for (int k = 0; k < 16; ++k) w = fmaf(Gm[i][k], Vn[k][j], w);
        Wb[i][j] = w;
        if (isv) {
            float s = mim_r;
#pragma unroll
            for (int k = 0; k < 16; ++k) s = fmaf(Gm[i][k], mn[k], s);
            mt_s[i] = s;
        }
        __syncthreads();                                   // b2

        // R3: Vt, outputs, stage GJ, klacc
        float v = pi_r;
#pragma unroll
        for (int k = 0; k < 16; ++k) v = fmaf(Wb[i][k], Gm[j][k], v);
        v_reg = v;
        float mti = mt_s[i];
        exxtO [(size_t)t * 256 + tid] = v + mti * mt_s[j];
        exxntO[(size_t)t * 256 + tid] = w + mti * mn[j];
        if (isv) {
            exO[(size_t)t * 16 + i]  = mti;
            scr3[(size_t)t * 16 + i] = mti;
        }
        if (isdiag) klacc += -0.5f * (jn_r + 0.5f) * (v + mti * mti) + hn_r * mti;
        Buf0[i][j]      = v;
        Buf0[i][j + 16] = w;
        __syncthreads();                                   // b3

        gj_block<false>(Buf0, Buf1, 0,  i, j);             // b4..b7
        gj_block<false>(Buf1, Buf0, 4,  i, j);
        gj_block<false>(Buf0, Buf1, 8,  i, j);
        gj_block<false>(Buf1, Buf0, 12, i, j);
        // Buf0 = [Vt^{-1} | K]

        // R8: condV, K^T store, stage chol
        float cv = Vn[i][j];
#pragma unroll
        for (int k = 0; k < 16; ++k) cv = fmaf(-Wb[k][i], Buf0[k][16 + j], cv);
        if (isdiag) cv += 1e-6f;
        scr1[(size_t)t * 256 + tid] = Buf0[j][16 + i];
        Buf1[i][j] = cv;
        __syncthreads();                                   // b8

        chol_block(Buf1, Buf0, 0,  i, j);                  // b9..b12
        chol_block(Buf0, Buf1, 4,  i, j);
        chol_block(Buf1, Buf0, 8,  i, j);
        chol_block(Buf0, Buf1, 12, i, j);
        // Buf1 = Ls

        // R1': Ls store, carry update, stage Gm, prefetch
        scr2[(size_t)t * 256 + tid] = (j <= i) ? Buf1[i][j] : 0.f;
        Vn[i][j] = v_reg;
        if (isv) mn[i] = mt_s[i];
        if (t > 0) {
            g_r  = scr2[(size_t)(t - 1) * 256 + tid];
            pi_r = scr1[(size_t)(t - 1) * 256 + tid];
            if (isv)    mim_r = scr3[(size_t)(t - 1) * 16 + i];
            if (isdiag) { jn_r = Jb[(t - 1) * 16 + i]; hn_r = Hb[(t - 1) * 16 + i]; }
            Gm[i][j] = g_r;
        }
        __syncthreads();                                   // b1
    }

    // ======================= SAMPLING =======================
    Buf0[i][j] = v_reg + (isdiag ? 1e-6f : 0.f);           // Vs[0] + jitter
    __syncthreads();
    chol_block(Buf0, Buf1, 0,  i, j);
    chol_block(Buf1, Buf0, 4,  i, j);
    chol_block(Buf0, Buf1, 8,  i, j);
    chol_block(Buf1, Buf0, 12, i, j);
    {
        float e0 = epsb[j];
        float v  = ((j <= i) ? Buf0[i][j] : 0.f) * e0;
        v += __shfl_xor_sync(0xffffffffu, v, 1);
        v += __shfl_xor_sync(0xffffffffu, v, 2);
        v += __shfl_xor_sync(0xffffffffu, v, 4);
        v += __shfl_xor_sync(0xffffffffu, v, 8);
        if (j == 0) { float x = mn[i] + v; xs[0][i] = x; zO[i] = x; }
    }
    __syncthreads();

    float kt_r  = scr1[tid];
    float ls_r  = scr2[tid];
    float mtj_r = scr3[j];
    float mni_r = scr3[16 + i];
    float ej_r  = epsb[16 + j];
    for (int t = 0; t < TM1; ++t) {
        float kt = kt_r, ls = ls_r, mtj = mtj_r, mni = mni_r, ej = ej_r;
        if (t + 1 < TM1) {
            kt_r  = scr1[(size_t)(t + 1) * 256 + tid];
            ls_r  = scr2[(size_t)(t + 1) * 256 + tid];
            mtj_r = scr3[(size_t)(t + 1) * 16 + j];
            mni_r = scr3[(size_t)(t + 2) * 16 + i];
            ej_r  = epsb[(size_t)(t + 2) * 16 + j];
        }
        float v = kt * (xs[t & 1][j] - mtj) + ls * ej;
        v += __shfl_xor_sync(0xffffffffu, v, 1);
        v += __shfl_xor_sync(0xffffffffu, v, 2);
        v += __shfl_xor_sync(0xffffffffu, v, 4);
        v += __shfl_xor_sync(0xffffffffu, v, 8);
        if (j == 0) {
            float x = mni + v;
            xs[(t & 1) ^ 1][i] = x;
            zO[(size_t)(t + 1) * 16 + i] = x;
        }
        __syncthreads();
    }

    // ---- final reductions: kl = klacc_total - (lzall + sum lzp) ----
    if (isdiag) red[i]      = klacc;
    if (isv)    red[16 + i] = lzp;
    __syncthreads();
    if (tid == 0) {
        float kls = 0.f, lzs = 0.f;
#pragma unroll
        for (int k = 0; k < 16; ++k) { kls += red[k]; lzs += red[16 + k]; }
        out[KL_OFF + b] = kls - (lzall + lzs);
    }
}

extern "C" void kernel_launch(void* const* d_in, const int* in_sizes, int n_in,
                              void* d_out, int out_size) {
    const float* Jr    = (const float*)d_in[0];
    const float* hr    = (const float*)d_in[1];
    const float* loc   = (const float*)d_in[2];
    const float* Tau_p = (const float*)d_in[3];
    const float* Lam_p = (const float*)d_in[4];
    const float* X     = (const float*)d_in[5];
    float* out = (float*)d_out;

    setup_kernel<<<1, 256>>>(loc, Tau_p, Lam_p, X);
    lds_main<<<BB, 256>>>(Jr, hr, out);
}

// round 14
// speedup vs baseline: 1.3527x; 1.1000x over previous
#include <cuda_runtime.h>
#include <cstdint>

#define TT   1000
#define TM1  999
#define BB   64

__device__ float g_tau[256], g_lam[256], g_AtL[256], g_AtLA[256];
__device__ float g_tau_mu[16], g_AtLb[16], g_Lb[16];
__device__ float g_consts[2];
__device__ unsigned g_keys[BB][2];

__device__ float g_scr1[(size_t)BB * TM1 * 256]; // fwd: Pi   -> bwd: K^T
__device__ float g_scr2[(size_t)BB * TM1 * 256]; // fwd: G    -> bwd: Ls
__device__ float g_scr3[(size_t)BB * TT  * 16];  // fwd: Mim  -> bwd: m_t (slot TM1=m_T)
__device__ float g_eps [(size_t)BB * TT  * 16];

__device__ __forceinline__ void tf2x32(unsigned k0, unsigned k1,
                                       unsigned x0, unsigned x1,
                                       unsigned &o0, unsigned &o1) {
    unsigned ks2 = k0 ^ k1 ^ 0x1BD11BDAu;
    x0 += k0; x1 += k1;
#define TFR(r) { x0 += x1; x1 = (x1 << (r)) | (x1 >> (32 - (r))); x1 ^= x0; }
    TFR(13) TFR(15) TFR(26) TFR(6)
    x0 += k1;  x1 += ks2 + 1u;
    TFR(17) TFR(29) TFR(16) TFR(24)
    x0 += ks2; x1 += k0 + 2u;
    TFR(13) TFR(15) TFR(26) TFR(6)
    x0 += k0;  x1 += k1 + 3u;
    TFR(17) TFR(29) TFR(16) TFR(24)
    x0 += k1;  x1 += ks2 + 4u;
    TFR(13) TFR(15) TFR(26) TFR(6)
    x0 += ks2; x1 += k0 + 5u;
#undef TFR
    o0 = x0; o1 = x1;
}

// ---- blocked GJ, 2 pivots [k,k+1], augmented [M(16)|R(16)|m]; C->N; sync; returns det ----
template <bool WITH_M>
__device__ __forceinline__ float gj_block2(const float (*C)[48], float (*N)[48],
                                           int k, int i, int j) {
    float p00 = C[k][k],     p01 = C[k][k + 1];
    float p10 = C[k + 1][k], p11 = C[k + 1][k + 1];
    float det = p00 * p11 - p01 * p10;
    float id  = __fdividef(1.f, det);
    float Di00 =  p11 * id, Di01 = -p01 * id;
    float Di10 = -p10 * id, Di11 =  p00 * id;
    float u0 = C[i][k], u1 = C[i][k + 1];

    // left column j
    {
        float res;
        if (j == k || j == k + 1) {
            float c0 = (j == k) ? Di00 : Di01;   // row k
            float c1 = (j == k) ? Di10 : Di11;   // row k+1
            if (i == k)          res = c0;
            else if (i == k + 1) res = c1;
            else                 res = -(u0 * c0 + u1 * c1);
        } else {
            float b0 = C[k][j], b1 = C[k + 1][j];
            float w0 = Di00 * b0 + Di01 * b1;
            float w1 = Di10 * b0 + Di11 * b1;
            if (i == k)          res = w0;
            else if (i == k + 1) res = w1;
            else                 res = C[i][j] - (u0 * w0 + u1 * w1);
        }
        N[i][j] = res;
    }
    // right column j+16 (never a pivot column)
    {
        float b0 = C[k][j + 16], b1 = C[k + 1][j + 16];
        float w0 = Di00 * b0 + Di01 * b1;
        float w1 = Di10 * b0 + Di11 * b1;
        float res;
        if (i == k)          res = w0;
        else if (i == k + 1) res = w1;
        else                 res = C[i][j + 16] - (u0 * w0 + u1 * w1);
        N[i][j + 16] = res;
    }
    if (WITH_M && j == 0) {
        float b0 = C[k][32], b1 = C[k + 1][32];
        float w0 = Di00 * b0 + Di01 * b1;
        float w1 = Di10 * b0 + Di11 * b1;
        float res;
        if (i == k)          res = w0;
        else if (i == k + 1) res = w1;
        else                 res = C[i][32] - (u0 * w0 + u1 * w1);
        N[i][32] = res;
    }
    __syncthreads();
    return det;
}

// ---- blocked Cholesky (lower), 2 columns [k,k+1]; C->N (left 16 cols); sync ----
__device__ __forceinline__ void chol_block2(const float (*C)[48], float (*N)[48],
                                            int k, int i, int j) {
    float r0  = rsqrtf(C[k][k]);
    float l10 = C[k + 1][k] * r0;
    float t11 = C[k + 1][k + 1] - l10 * l10;
    float r1  = rsqrtf(t11);

    float res = C[i][j];
    if (j >= k) {
        float p0 = C[i][k] * r0;
        float p1 = (C[i][k + 1] - p0 * l10) * r1;
        if (j == k) {
            if (i >= k) res = p0;
        } else if (j == k + 1) {
            if (i >= k + 1) res = p1;
        } else if (i >= j) {
            float q0 = C[j][k] * r0;
            float q1 = (C[j][k + 1] - q0 * l10) * r1;
            res = res - p0 * q0 - p1 * q1;
        }
    }
    N[i][j] = res;
    __syncthreads();
}

__device__ float logdet16_local(const float M[16][17]) {
    float a[16][16];
    for (int r = 0; r < 16; ++r)
        for (int c = 0; c < 16; ++c) a[r][c] = M[r][c];
    float ld = 0.f;
    for (int k = 0; k < 16; ++k) {
        float p = a[k][k];
        ld += logf(p);
        float pi_ = __fdiv_rn(1.f, p);
        for (int r = k + 1; r < 16; ++r) {
            float f = a[r][k] * pi_;
            for (int c = k + 1; c < 16; ++c) a[r][c] = fmaf(-f, a[k][c], a[r][c]);
        }
    }
    return ld;
}

__global__ void __launch_bounds__(256) setup_kernel(const float* __restrict__ loc,
                                                    const float* __restrict__ Tau_p,
                                                    const float* __restrict__ Lam_p,
                                                    const float* __restrict__ X) {
    __shared__ float sTau[16][17], sLamS[16][17], sA[16][17], sAtLs[16][17];
    __shared__ float sbv[16], slocv[16];
    int tid = threadIdx.x, i = tid >> 4, j = tid & 15;

    float t = 0.f, l = 0.f;
#pragma unroll
    for (int k = 0; k < 16; ++k) {
        t = fmaf(Tau_p[i * 16 + k], Tau_p[j * 16 + k], t);
        l = fmaf(Lam_p[i * 16 + k], Lam_p[j * 16 + k], l);
    }
    if (i == j) { t += 1e-8f; l += 1e-8f; }
    sTau[i][j] = t; sLamS[i][j] = l;
    sA[i][j]   = X[i * 17 + j];
    if (tid < 16) { sbv[tid] = X[tid * 17 + 16]; slocv[tid] = loc[tid]; }
    __syncthreads();

    float atl = 0.f;
#pragma unroll
    for (int k = 0; k < 16; ++k) atl = fmaf(sA[k][i], sLamS[k][j], atl);
    sAtLs[i][j] = atl;
    __syncthreads();

    float atla = 0.f;
#pragma unroll
    for (int k = 0; k < 16; ++k) atla = fmaf(sAtLs[i][k], sA[k][j], atla);

    g_tau[tid] = t; g_lam[tid] = l; g_AtL[tid] = atl; g_AtLA[tid] = atla;

    if (tid < 16) {
        float tm = 0.f, alb = 0.f, lb = 0.f;
#pragma unroll
        for (int k = 0; k < 16; ++k) {
            tm  = fmaf(sTau[tid][k],  slocv[k], tm);
            alb = fmaf(sAtLs[tid][k], sbv[k],   alb);
            lb  = fmaf(sLamS[tid][k], sbv[k],   lb);
        }
        g_tau_mu[tid] = tm; g_AtLb[tid] = alb; g_Lb[tid] = lb;
    }
    if (tid < BB) {
        unsigned o0, o1;
        tf2x32(0u, 42u, 0u, (unsigned)tid, o0, o1);
        g_keys[tid][0] = o0; g_keys[tid][1] = o1;
    }
    __syncthreads();
    if (tid == 0) {
        float ldl = logdet16_local(sLamS);
        float ldt = logdet16_local(sTau);
        float bLb = 0.f, ltm = 0.f;
        for (int k = 0; k < 16; ++k) {
            bLb = fmaf(sbv[k],   g_Lb[k],     bLb);
            ltm = fmaf(slocv[k], g_tau_mu[k], ltm);
        }
        g_consts[0] = -0.5f * bLb + 0.5f * ldl;
        g_consts[1] = -0.5f * ltm + 0.5f * ldt;
    }
}

__global__ void __launch_bounds__(256, 1) lds_main(const float* __restrict__ Jr,
                                                   const float* __restrict__ hr,
                                                   float* __restrict__ out) {
    const int b   = blockIdx.x;
    const int tid = threadIdx.x;
    const int i   = tid >> 4, j = tid & 15;
    const bool isdiag = (i == j);
    const bool isv    = (j == 0);

    const float trans_const = g_consts[0];
    const float init_const  = g_consts[1];

    const float* Jb = Jr + (size_t)b * TT * 16;
    const float* Hb = hr + (size_t)b * TT * 16;
    float* scr1 = g_scr1 + (size_t)b * TM1 * 256;
    float* scr2 = g_scr2 + (size_t)b * TM1 * 256;
    float* scr3 = g_scr3 + (size_t)b * TT * 16;
    float* epsb = g_eps  + (size_t)b * TT * 16;

    const size_t KL_OFF    = (size_t)BB * TT * 16;
    const size_t EXXT_OFF  = KL_OFF + BB;
    const size_t EX_OFF    = EXXT_OFF + (size_t)BB * TT * 256;
    const size_t EXXNT_OFF = EX_OFF + (size_t)BB * TT * 16;
    float* zO     = out + (size_t)b * TT * 16;
    float* exxtO  = out + EXXT_OFF + (size_t)b * TT * 256;
    float* exO    = out + EX_OFF + (size_t)b * TT * 16;
    float* exxntO = out + EXXNT_OFF + (size_t)b * TM1 * 256;

    __shared__ float Buf0[16][48], Buf1[16][48];
    __shared__ float sAtL[16][17];
    __shared__ float Gm[16][17], Wb[16][17], Vn[16][17];
    __shared__ float mt_s[16], mn[16], mT_s[16];
    __shared__ float xs[2][16];
    __shared__ float red[32];

    // ---- epsilon generation ----
    {
        unsigned k0 = g_keys[b][0], k1 = g_keys[b][1];
        for (int idx = tid; idx < TT * 16; idx += 256) {
            unsigned o0, o1;
            tf2x32(k0, k1, 0u, (unsigned)idx, o0, o1);
            unsigned bits = o0 ^ o1;
            float f = __uint_as_float((bits >> 9) | 0x3f800000u) - 1.0f;
            const float lo = -0.99999994f;
            float v = fmaxf(lo, f * 2.0f + lo);
            epsb[idx] = 1.4142135623730951f * erfinvf(v);
        }
    }

    const float lam_r  = g_lam[tid];
    const float atla_r = g_AtLA[tid];
    const float atl_r  = g_AtL[tid];
    sAtL[i][j] = atl_r;
    const float lb_r   = g_Lb[i];
    const float atlb_r = g_AtLb[i];

    float lzall = 0.f;       // all threads (identical)
    float lzp   = 0.f;       // j==0 threads
    float klacc = 0.f;       // diag threads
    float jn_r = 0.f, hn_r = 0.f;
    float mv_r = 0.f;

    // ---- pre-stage step 0 ----
    {
        float fJ0 = g_tau[tid] + (isdiag ? (Jb[i] + 0.5f) : 0.f);
        Buf0[i][j]      = fJ0 + atla_r;
        Buf0[i][j + 16] = atl_r;
        if (isv) {
            float fh0 = g_tau_mu[i] + Hb[i];
            mv_r = fh0 - atlb_r;
            Buf0[i][32] = mv_r;
        }
        if (isdiag || isv) { jn_r = Jb[16 + i]; hn_r = Hb[16 + i]; }
    }
    __syncthreads();

    float (*S)[48] = Buf0;
    float (*R)[48] = Buf1;

    // ======================= FORWARD (9 regions/step) =======================
    for (int t = 0; t < TM1; ++t) {
        float d0 = gj_block2<true>(S, R, 0,  i, j);
        float d1 = gj_block2<true>(R, S, 2,  i, j);
        float d2 = gj_block2<true>(S, R, 4,  i, j);
        float d3 = gj_block2<true>(R, S, 6,  i, j);
        float d4 = gj_block2<true>(S, R, 8,  i, j);
        float d5 = gj_block2<true>(R, S, 10, i, j);
        float d6 = gj_block2<true>(S, R, 12, i, j);
        float d7 = gj_block2<true>(R, S, 14, i, j);
        // S = [Pi | G | Mim]
        lzall += trans_const - 0.5f * (__logf(d0 * d1 * d2 * d3) + __logf(d4 * d5 * d6 * d7));

        const bool term = (t == TM1 - 1);
        scr1[(size_t)t * 256 + tid] = S[i][j];
        scr2[(size_t)t * 256 + tid] = S[i][16 + j];

        float na = lam_r, nb = 0.f;
#pragma unroll
        for (int k = 0; k < 8; ++k)  na = fmaf(-sAtL[k][i], S[k][16 + j], na);
#pragma unroll
        for (int k = 8; k < 16; ++k) nb = fmaf(-sAtL[k][i], S[k][16 + j], nb);
        R[i][j]      = (na + nb) + (isdiag ? (jn_r + 0.5f) : 0.f) + (term ? 0.f : atla_r);
        R[i][j + 16] = atl_r;

        if (isv) {
            float mim_i = S[i][32];
            scr3[(size_t)t * 16 + i] = mim_i;
            lzp += 0.5f * mv_r * mim_i;
            float fa = lb_r + hn_r, fb = 0.f;
#pragma unroll
            for (int k = 0; k < 8; ++k)  fa = fmaf(sAtL[k][i], S[k][32], fa);
#pragma unroll
            for (int k = 8; k < 16; ++k) fb = fmaf(sAtL[k][i], S[k][32], fb);
            float fh_new = fa + fb;
            mv_r = term ? fh_new : (fh_new - atlb_r);
            R[i][32] = mv_r;
        }
        if ((isdiag || isv) && (t + 2 < TT)) {
            jn_r = Jb[(t + 2) * 16 + i];
            hn_r = Hb[(t + 2) * 16 + i];
        }
        __syncthreads();
        float (*tmp)[48] = S; S = R; R = tmp;
    }

    // ---- terminal inversion: S holds [fJ_T | AtL | fh_T] ----
    {
        float d0 = gj_block2<true>(S, R, 0,  i, j);
        float d1 = gj_block2<true>(R, S, 2,  i, j);
        float d2 = gj_block2<true>(S, R, 4,  i, j);
        float d3 = gj_block2<true>(R, S, 6,  i, j);
        float d4 = gj_block2<true>(S, R, 8,  i, j);
        float d5 = gj_block2<true>(R, S, 10, i, j);
        float d6 = gj_block2<true>(S, R, 12, i, j);
        float d7 = gj_block2<true>(R, S, 14, i, j);
        lzall += init_const - 0.5f * (__logf(d0 * d1 * d2 * d3) + __logf(d4 * d5 * d6 * d7));
    }
    if (isv) {
        float mT = S[i][32];
        mT_s[i] = mT;
        lzp += 0.5f * mv_r * mT;
        exO[(size_t)(TT - 1) * 16 + i] = mT;
        scr3[(size_t)TM1 * 16 + i]     = mT;
    }
    __syncthreads();
    {
        float vT = S[i][j];
        float mTi = mT_s[i], mTj = mT_s[j];
        exxtO[(size_t)(TT - 1) * 256 + tid] = vT + mTi * mTj;
        Vn[i][j] = vT;
        if (isdiag) klacc += -0.5f * (jn_r + 0.5f) * (vT + mTi * mTi) + hn_r * mTi;
        if (isv) mn[i] = mT_s[i];
    }
    float g_r  = scr2[(size_t)(TM1 - 1) * 256 + tid];
    float pi_r = scr1[(size_t)(TM1 - 1) * 256 + tid];
    float mim_r = 0.f;
    if (isv)    mim_r = scr3[(size_t)(TM1 - 1) * 16 + i];
    if (isdiag) { jn_r = Jb[(TM1 - 1) * 16 + i]; hn_r = Hb[(TM1 - 1) * 16 + i]; }
    Gm[i][j] = g_r;
    __syncthreads();

    float v_reg = 0.f;
    // ======================= BACKWARD (20 regions/step) =======================
    for (int t = TM1 - 1; t >= 0; --t) {
        // R2: Wb = G Vn ; mt
        float wa = 0.f, wbp = 0.f;
#pragma unroll
        for (int k = 0; k < 8; ++k)  wa  = fmaf(Gm[i][k], Vn[k][j], wa);
#pragma unroll
        for (int k = 8; k < 16; ++k) wbp = fmaf(Gm[i][k], Vn[k][j], wbp);
        float w = wa + wbp;
        Wb[i][j] = w;
        if (isv) {
            float sa = mim_r, sb = 0.f;
#pragma unroll
            for (int k = 0; k < 8; ++k)  sa = fmaf(Gm[i][k], mn[k], sa);
#pragma unroll
            for (int k = 8; k < 16; ++k) sb = fmaf(Gm[i][k], mn[k], sb);
            mt_s[i] = sa + sb;
        }
        __syncthreads();                                   // b2

        // R3: Vt, outputs, stage GJ, klacc
        float va = pi_r, vb = 0.f;
#pragma unroll
        for (int k = 0; k < 8; ++k)  va = fmaf(Wb[i][k], Gm[j][k], va);
#pragma unroll
        for (int k = 8; k < 16; ++k) vb = fmaf(Wb[i][k], Gm[j][k], vb);
        float v = va + vb;
        v_reg = v;
        float mti = mt_s[i];
        exxtO [(size_t)t * 256 + tid] = v + mti * mt_s[j];
        exxntO[(size_t)t * 256 + tid] = w + mti * mn[j];
        if (isv) {
            exO[(size_t)t * 16 + i]  = mti;
            scr3[(size_t)t * 16 + i] = mti;
        }
        if (isdiag) klacc += -0.5f * (jn_r + 0.5f) * (v + mti * mti) + hn_r * mti;
        Buf0[i][j]      = v;
        Buf0[i][j + 16] = w;
        __syncthreads();                                   // b3

        gj_block2<false>(Buf0, Buf1, 0,  i, j);
        gj_block2<false>(Buf1, Buf0, 2,  i, j);
        gj_block2<false>(Buf0, Buf1, 4,  i, j);
        gj_block2<false>(Buf1, Buf0, 6,  i, j);
        gj_block2<false>(Buf0, Buf1, 8,  i, j);
        gj_block2<false>(Buf1, Buf0, 10, i, j);
        gj_block2<false>(Buf0, Buf1, 12, i, j);
        gj_block2<false>(Buf1, Buf0, 14, i, j);
        // Buf0 = [Vt^{-1} | K]

        // R8: condV, K^T store, stage chol
        float ca = Vn[i][j], cb = 0.f;
#pragma unroll
        for (int k = 0; k < 8; ++k)  ca = fmaf(-Wb[k][i], Buf0[k][16 + j], ca);
#pragma unroll
        for (int k = 8; k < 16; ++k) cb = fmaf(-Wb[k][i], Buf0[k][16 + j], cb);
        float cv = ca + cb;
        if (isdiag) cv += 1e-6f;
        scr1[(size_t)t * 256 + tid] = Buf0[j][16 + i];
        Buf1[i][j] = cv;
        __syncthreads();                                   // b8

        chol_block2(Buf1, Buf0, 0,  i, j);
        chol_block2(Buf0, Buf1, 2,  i, j);
        chol_block2(Buf1, Buf0, 4,  i, j);
        chol_block2(Buf0, Buf1, 6,  i, j);
        chol_block2(Buf1, Buf0, 8,  i, j);
        chol_block2(Buf0, Buf1, 10, i, j);
        chol_block2(Buf1, Buf0, 12, i, j);
        chol_block2(Buf0, Buf1, 14, i, j);
        // Buf1 = Ls

        // R1': Ls store, carry update, stage Gm, prefetch
        scr2[(size_t)t * 256 + tid] = (j <= i) ? Buf1[i][j] : 0.f;
        Vn[i][j] = v_reg;
        if (isv) mn[i] = mt_s[i];
        if (t > 0) {
            g_r  = scr2[(size_t)(t - 1) * 256 + tid];
            pi_r = scr1[(size_t)(t - 1) * 256 + tid];
            if (isv)    mim_r = scr3[(size_t)(t - 1) * 16 + i];
            if (isdiag) { jn_r = Jb[(t - 1) * 16 + i]; hn_r = Hb[(t - 1) * 16 + i]; }
            Gm[i][j] = g_r;
        }
        __syncthreads();                                   // b1
    }

    // ======================= SAMPLING =======================
    Buf0[i][j] = v_reg + (isdiag ? 1e-6f : 0.f);           // Vs[0] + jitter
    __syncthreads();
    chol_block2(Buf0, Buf1, 0,  i, j);
    chol_block2(Buf1, Buf0, 2,  i, j);
    chol_block2(Buf0, Buf1, 4,  i, j);
    chol_block2(Buf1, Buf0, 6,  i, j);
    chol_block2(Buf0, Buf1, 8,  i, j);
    chol_block2(Buf1, Buf0, 10, i, j);
    chol_block2(Buf0, Buf1, 12, i, j);
    chol_block2(Buf1, Buf0, 14, i, j);
    {
        float e0 = epsb[j];
        float v  = ((j <= i) ? Buf0[i][j] : 0.f) * e0;
        v += __shfl_xor_sync(0xffffffffu, v, 1);
        v += __shfl_xor_sync(0xffffffffu, v, 2);
        v += __shfl_xor_sync(0xffffffffu, v, 4);
        v += __shfl_xor_sync(0xffffffffu, v, 8);
        if (j == 0) { float x = mn[i] + v; xs[0][i] = x; zO[i] = x; }
    }
    __syncthreads();

    float kt_r  = scr1[tid];
    float ls_r  = scr2[tid];
    float mtj_r = scr3[j];
    float mni_r = scr3[16 + i];
    float ej_r  = epsb[16 + j];
    for (int t = 0; t < TM1; ++t) {
        float kt = kt_r, ls = ls_r, mtj = mtj_r, mni = mni_r, ej = ej_r;
        if (t + 1 < TM1) {
            kt_r  = scr1[(size_t)(t + 1) * 256 + tid];
            ls_r  = scr2[(size_t)(t + 1) * 256 + tid];
            mtj_r = scr3[(size_t)(t + 1) * 16 + j];
            mni_r = scr3[(size_t)(t + 2) * 16 + i];
            ej_r  = epsb[(size_t)(t + 2) * 16 + j];
        }
        float v = kt * (xs[t & 1][j] - mtj) + ls * ej;
        v += __shfl_xor_sync(0xffffffffu, v, 1);
        v += __shfl_xor_sync(0xffffffffu, v, 2);
        v += __shfl_xor_sync(0xffffffffu, v, 4);
        v += __shfl_xor_sync(0xffffffffu, v, 8);
        if (j == 0) {
            float x = mni + v;
            xs[(t & 1) ^ 1][i] = x;
            zO[(size_t)(t + 1) * 16 + i] = x;
        }
        __syncthreads();
    }

    // ---- final reductions ----
    if (isdiag) red[i]      = klacc;
    if (isv)    red[16 + i] = lzp;
    __syncthreads();
    if (tid == 0) {
        float kls = 0.f, lzs = 0.f;
#pragma unroll
        for (int k = 0; k < 16; ++k) { kls += red[k]; lzs += red[16 + k]; }
        out[KL_OFF + b] = kls - (lzall + lzs);
    }
}

extern "C" void kernel_launch(void* const* d_in, const int* in_sizes, int n_in,
                              void* d_out, int out_size) {
    const float* Jr    = (const float*)d_in[0];
    const float* hr    = (const float*)d_in[1];
    const float* loc   = (const float*)d_in[2];
    const float* Tau_p = (const float*)d_in[3];
    const float* Lam_p = (const float*)d_in[4];
    const float* X     = (const float*)d_in[5];
    float* out = (float*)d_out;

    setup_kernel<<<1, 256>>>(loc, Tau_p, Lam_p, X);
    lds_main<<<BB, 256>>>(Jr, hr, out);
}